// round 15
// baseline (speedup 1.0000x reference)
#include <cuda_runtime.h>
#include <cuda_bf16.h>
#include <math.h>
#include <cstdint>

// Problem constants
#define BB   4
#define DIMC 256
#define HH   64
#define WW   64
#define HWSZ 4096
#define NHD  8
#define HDC  32
#define NPP  8
#define NG   (BB * HWSZ)      // 16384 tokens

// ---------------------------------------------------------------------------
// Scratch (device globals: no allocation allowed)
// ---------------------------------------------------------------------------
__device__ __align__(16) unsigned short g_qh[NG * DIMC];   // query bf16 hi, token-major
__device__ __align__(16) unsigned short g_ql[NG * DIMC];   // query bf16 lo
__device__ __align__(16) unsigned short g_vh[NG * DIMC];   // value bf16 hi
__device__ __align__(16) unsigned short g_vl[NG * DIMC];   // value bf16 lo
__device__ __align__(16) unsigned short g_mh[NG * DIMC];   // msda bf16 hi
__device__ __align__(16) unsigned short g_ml[NG * DIMC];   // msda bf16 lo
__device__ __align__(16) unsigned short g_w1h[256 * DIMC]; // [Wloc;Watt;pad0] hi
__device__ __align__(16) unsigned short g_w1l[256 * DIMC];
__device__ __align__(16) unsigned short g_w3h[256 * DIMC]; // Wval hi
__device__ __align__(16) unsigned short g_w3l[256 * DIMC];
__device__ __align__(16) unsigned short g_w0h[256 * DIMC]; // Wout hi
__device__ __align__(16) unsigned short g_w0l[256 * DIMC];

__device__ float g_vp [BB * NHD * HWSZ * HDC];   // v_proj, [b][h][yx][d]
__device__ float g_loc[NG * 128];                // loc logits, token-major
__device__ float g_att[NG * 64];                 // att logits, token-major

// ---------------------------------------------------------------------------
// helpers (plain sm_103-compatible: ldmatrix + mma.sync + cp.async)
// ---------------------------------------------------------------------------
__device__ __forceinline__ uint32_t smem_u32(const void* p) {
    uint32_t a;
    asm("{ .reg .u64 t; cvta.to.shared.u64 t, %1; cvt.u32.u64 %0, t; }" : "=r"(a) : "l"(p));
    return a;
}
__device__ __forceinline__ void ldsm_x4(uint32_t (&r)[4], uint32_t addr) {
    asm volatile("ldmatrix.sync.aligned.m8n8.x4.shared.b16 {%0,%1,%2,%3}, [%4];"
        : "=r"(r[0]), "=r"(r[1]), "=r"(r[2]), "=r"(r[3]) : "r"(addr));
}
__device__ __forceinline__ void mma16816(float (&c)[4], const uint32_t (&a)[4],
                                         uint32_t b0, uint32_t b1) {
    asm volatile("mma.sync.aligned.m16n8k16.row.col.f32.bf16.bf16.f32 "
        "{%0,%1,%2,%3}, {%4,%5,%6,%7}, {%8,%9}, {%0,%1,%2,%3};"
        : "+f"(c[0]), "+f"(c[1]), "+f"(c[2]), "+f"(c[3])
        : "r"(a[0]), "r"(a[1]), "r"(a[2]), "r"(a[3]), "r"(b0), "r"(b1));
}
#define CP16(dst_u32, src_ptr) \
    asm volatile("cp.async.cg.shared.global [%0], [%1], 16;" :: "r"(dst_u32), "l"(src_ptr))
#define CP_COMMIT() asm volatile("cp.async.commit_group;" ::: "memory")
#define CP_WAIT0()  asm volatile("cp.async.wait_group 0;" ::: "memory")

__device__ __forceinline__ void pack_hilo4(float4 v, uint2& hi, uint2& lo) {
    __nv_bfloat16 h0 = __float2bfloat16(v.x), h1 = __float2bfloat16(v.y);
    __nv_bfloat16 h2 = __float2bfloat16(v.z), h3 = __float2bfloat16(v.w);
    __nv_bfloat16 l0 = __float2bfloat16(v.x - __bfloat162float(h0));
    __nv_bfloat16 l1 = __float2bfloat16(v.y - __bfloat162float(h1));
    __nv_bfloat16 l2 = __float2bfloat16(v.z - __bfloat162float(h2));
    __nv_bfloat16 l3 = __float2bfloat16(v.w - __bfloat162float(h3));
    hi.x = ((uint32_t)__bfloat16_as_ushort(h1) << 16) | __bfloat16_as_ushort(h0);
    hi.y = ((uint32_t)__bfloat16_as_ushort(h3) << 16) | __bfloat16_as_ushort(h2);
    lo.x = ((uint32_t)__bfloat16_as_ushort(l1) << 16) | __bfloat16_as_ushort(l0);
    lo.y = ((uint32_t)__bfloat16_as_ushort(l3) << 16) | __bfloat16_as_ushort(l2);
}

// ---------------------------------------------------------------------------
// convert_act: transpose query/value [b][k][4096] fp32 -> token-major bf16 hi/lo
// ---------------------------------------------------------------------------
__global__ __launch_bounds__(256)
void convert_act(const float* __restrict__ q, const float* __restrict__ v)
{
    __shared__ float sm[256 * 33];
    const int bi = blockIdx.x;
    const int tensor = bi >> 9;
    const int rem = bi & 511;
    const int b = rem >> 7, tile = rem & 127;
    const float* src = (tensor ? v : q) + (size_t)b * DIMC * HWSZ + tile * 32;

    for (int idx = threadIdx.x; idx < 2048; idx += 256) {
        const int k = idx >> 3, t4 = (idx & 7) * 4;
        const float4 val = *(const float4*)(src + (size_t)k * HWSZ + t4);
        sm[k * 33 + t4 + 0] = val.x;
        sm[k * 33 + t4 + 1] = val.y;
        sm[k * 33 + t4 + 2] = val.z;
        sm[k * 33 + t4 + 3] = val.w;
    }
    __syncthreads();

    unsigned short* dh = tensor ? g_vh : g_qh;
    unsigned short* dl = tensor ? g_vl : g_ql;
    const size_t g0 = (size_t)b * HWSZ + tile * 32;

    for (int idx = threadIdx.x; idx < 1024; idx += 256) {
        const int t = idx >> 5, k8 = (idx & 31) * 8;
        float4 v0, v1;
        v0.x = sm[(k8 + 0) * 33 + t]; v0.y = sm[(k8 + 1) * 33 + t];
        v0.z = sm[(k8 + 2) * 33 + t]; v0.w = sm[(k8 + 3) * 33 + t];
        v1.x = sm[(k8 + 4) * 33 + t]; v1.y = sm[(k8 + 5) * 33 + t];
        v1.z = sm[(k8 + 6) * 33 + t]; v1.w = sm[(k8 + 7) * 33 + t];
        uint2 h0, l0, h1, l1;
        pack_hilo4(v0, h0, l0); pack_hilo4(v1, h1, l1);
        *(uint4*)(dh + (g0 + t) * DIMC + k8) = make_uint4(h0.x, h0.y, h1.x, h1.y);
        *(uint4*)(dl + (g0 + t) * DIMC + k8) = make_uint4(l0.x, l0.y, l1.x, l1.y);
    }
}

// ---------------------------------------------------------------------------
// convert_w: weights fp32 -> bf16 hi/lo planes. 768 rows:
// [0,256): g_w1 = [Wloc(128); Watt(64); zeros(64)], [256,512): Wval, [512,768): Wout
// ---------------------------------------------------------------------------
__global__ __launch_bounds__(256)
void convert_w(const float* __restrict__ Wloc, const float* __restrict__ Watt,
               const float* __restrict__ Wval, const float* __restrict__ Wout)
{
    const int idx = blockIdx.x * 256 + threadIdx.x;   // one item = 8 elements
    if (idx >= 768 * 32) return;
    const int r = idx >> 5, k8 = (idx & 31) * 8;
    const float* src = nullptr;
    unsigned short *dh, *dl;
    if (r < 256) {
        if (r < 128)      src = Wloc + (size_t)r * DIMC;
        else if (r < 192) src = Watt + (size_t)(r - 128) * DIMC;
        dh = g_w1h + (size_t)r * DIMC; dl = g_w1l + (size_t)r * DIMC;
    } else if (r < 512) {
        const int rr = r - 256;
        src = Wval + (size_t)rr * DIMC;
        dh = g_w3h + (size_t)rr * DIMC; dl = g_w3l + (size_t)rr * DIMC;
    } else {
        const int rr = r - 512;
        src = Wout + (size_t)rr * DIMC;
        dh = g_w0h + (size_t)rr * DIMC; dl = g_w0l + (size_t)rr * DIMC;
    }
    uint2 h0, l0, h1, l1;
    if (src) {
        const float4 v0 = *(const float4*)(src + k8);
        const float4 v1 = *(const float4*)(src + k8 + 4);
        pack_hilo4(v0, h0, l0); pack_hilo4(v1, h1, l1);
    } else {
        h0 = l0 = h1 = l1 = make_uint2(0u, 0u);
    }
    *(uint4*)(dh + k8) = make_uint4(h0.x, h0.y, h1.x, h1.y);
    *(uint4*)(dl + k8) = make_uint4(l0.x, l0.y, l1.x, l1.y);
}

// ---------------------------------------------------------------------------
// bf16-split tensor-core GEMM: MT=128, NT=128, 256 threads, 2 CTAs/SM.
// ONE 64KB smem buffer, K64 chunks; load exposed per-CTA, hidden by co-resident CTA.
// D[m0..+128][ny0..+128] = A[m][256] . W[n][256]^T + bias
// DST: 1 = loc/att (padded W1; n<128 -> g_loc, 128<=n<192 -> g_att)
//      3 = vproj -> g_vp per-head layout
//      0 = out   -> Cout ldc=256
// ---------------------------------------------------------------------------
template<int DST>
__global__ __launch_bounds__(256, 2)
void tc_gemm(const float* __restrict__ bias1, const float* __restrict__ bias2,
             float* __restrict__ Cout)
{
    constexpr int NTH = 256;

    extern __shared__ char smraw[];
    const uint32_t sb    = smem_u32(smraw);
    const uint32_t sbase = (sb + 1023) & ~1023u;
    char* smc = smraw + (sbase - sb);

    const int tid  = threadIdx.x;
    const int lane = tid & 31;
    const int wid  = tid >> 5;
    const int wm   = wid & 1;        // 2 warp-rows (64 tokens each)
    const int wn   = wid >> 1;       // 4 warp-cols (32 cols each)

    const int m0  = blockIdx.x * 128;
    const int ny0 = blockIdx.y * 128;
    const int b   = m0 >> 12;
    const int yx0 = m0 & (HWSZ - 1);

    const char* Ah = (const char*)((DST == 1) ? g_qh : (DST == 3) ? g_vh : g_mh);
    const char* Al = (const char*)((DST == 1) ? g_ql : (DST == 3) ? g_vl : g_ml);
    const char* Wh = (const char*)((DST == 1) ? g_w1h : (DST == 3) ? g_w3h : g_w0h);
    const char* Wl = (const char*)((DST == 1) ? g_w1l : (DST == 3) ? g_w3l : g_w0l);

    // smem layout (one buffer): Ah[16K] Al[16K] Bh[16K] Bl[16K]
    auto load_chunk_async = [&](int c) {
        const int kB = c * 128;   // chunk byte offset within a 512B k-row
        for (int idx = tid; idx < 1024; idx += NTH) {
            const int t = idx >> 3, ko = idx & 7;
            const size_t go = (size_t)(m0 + t) * 512 + kB + ko * 16;
            const uint32_t off = t * 128 + ((ko * 16) ^ ((t & 7) << 4));
            CP16(sbase + off, Ah + go);
            CP16(sbase + 16384 + off, Al + go);
        }
        for (int idx = tid; idx < 1024; idx += NTH) {
            const int n = idx >> 3, ko = idx & 7;
            const size_t go = (size_t)(ny0 + n) * 512 + kB + ko * 16;
            const uint32_t off = n * 128 + ((ko * 16) ^ ((n & 7) << 4));
            CP16(sbase + 32768 + off, Wh + go);
            CP16(sbase + 49152 + off, Wl + go);
        }
        CP_COMMIT();
    };

    float acc[4][4][4];
    #pragma unroll
    for (int i = 0; i < 4; i++)
        #pragma unroll
        for (int j = 0; j < 4; j++)
            #pragma unroll
            for (int q = 0; q < 4; q++) acc[i][j][q] = 0.f;

    const uint32_t khb = (lane >> 4) * 16;    // ldmatrix k-half (bytes)

    for (int c = 0; c < 4; c++) {
        load_chunk_async(c);
        CP_WAIT0();
        __syncthreads();
        #pragma unroll
        for (int ks = 0; ks < 4; ks++) {
            const uint32_t kb = ks * 32 + khb;
            uint32_t bh[2][4], bl[2][4];
            #pragma unroll
            for (int np = 0; np < 2; np++) {
                const int nr = wn * 32 + np * 16 + (lane & 15);
                const uint32_t off = nr * 128 + (kb ^ ((nr & 7) << 4));
                ldsm_x4(bh[np], sbase + 32768 + off);
                ldsm_x4(bl[np], sbase + 49152 + off);
            }
            #pragma unroll
            for (int mt = 0; mt < 4; mt++) {
                const int mr = wm * 64 + mt * 16 + (lane & 15);
                const uint32_t off = mr * 128 + (kb ^ ((mr & 7) << 4));
                uint32_t ahf[4], alf[4];
                ldsm_x4(ahf, sbase + off);
                ldsm_x4(alf, sbase + 16384 + off);
                #pragma unroll
                for (int nt = 0; nt < 4; nt++) {
                    const int np = nt >> 1, hf = nt & 1;
                    mma16816(acc[mt][nt], ahf, bh[np][hf], bh[np][2 + hf]);
                    mma16816(acc[mt][nt], alf, bh[np][hf], bh[np][2 + hf]);
                    mma16816(acc[mt][nt], ahf, bl[np][hf], bl[np][2 + hf]);
                }
            }
        }
        __syncthreads();   // all reads done before next chunk overwrites
    }

    // ---- epilogue: frags -> smem stage -> (+bias) coalesced global store ----
    constexpr int NTP = 132;
    float* stage = (float*)smc;
    #pragma unroll
    for (int mt = 0; mt < 4; mt++) {
        const int r = wm * 64 + mt * 16 + (lane >> 2);
        #pragma unroll
        for (int nt = 0; nt < 4; nt++) {
            const int cl = wn * 32 + nt * 8 + (lane & 3) * 2;
            stage[r * NTP + cl]           = acc[mt][nt][0];
            stage[r * NTP + cl + 1]       = acc[mt][nt][1];
            stage[(r + 8) * NTP + cl]     = acc[mt][nt][2];
            stage[(r + 8) * NTP + cl + 1] = acc[mt][nt][3];
        }
    }
    __syncthreads();

    for (int idx = tid; idx < 128 * 32; idx += NTH) {
        const int t  = idx >> 5;
        const int nl = (idx & 31) * 4;
        const int n  = ny0 + nl;
        if (DST == 1 && n >= 192) continue;
        float4 v = *(const float4*)(stage + t * NTP + nl);
        float4 bb4;
        if (DST == 1) bb4 = (n < 128) ? *(const float4*)(bias1 + n)
                                      : *(const float4*)(bias2 + (n - 128));
        else          bb4 = *(const float4*)(bias1 + n);
        v.x += bb4.x; v.y += bb4.y; v.z += bb4.z; v.w += bb4.w;
        if (DST == 3) {
            const int h = n >> 5, d = n & 31;
            *(float4*)(g_vp + ((size_t)((b * NHD + h) * HWSZ) + yx0 + t) * HDC + d) = v;
        } else if (DST == 1) {
            if (n < 128) *(float4*)(g_loc + (size_t)(m0 + t) * 128 + n) = v;
            else         *(float4*)(g_att + (size_t)(m0 + t) * 64 + (n - 128)) = v;
        } else {
            *(float4*)(Cout + (size_t)(m0 + t) * 256 + n) = v;
        }
    }
}

// ---------------------------------------------------------------------------
// Sampling, phase-split (unchanged from R13)
// ---------------------------------------------------------------------------
__global__ __launch_bounds__(256)
void sampling_kernel()
{
    extern __shared__ float sms[];
    float4*   swgt4 = (float4*)sms;                    // [8*256]
    float*    smout = sms + 4 * 8 * 256;               // [32][256]
    uint32_t* spak  = (uint32_t*)(smout + 32 * 256);   // [8*256]

    const int tid  = threadIdx.x;
    const int g0   = blockIdx.x * 32;
    const int b    = g0 >> 12;
    const int w    = tid >> 5;
    const int lane = tid & 31;

    // ---- Phase 1: pair = tid (t = tid>>3, h = tid&7) ----
    {
        const int t = tid >> 3, h = tid & 7;
        float e[NPP];
        const float4 a0 = *(const float4*)(g_att + (size_t)(g0 + t) * 64 + h * 8);
        const float4 a1 = *(const float4*)(g_att + (size_t)(g0 + t) * 64 + h * 8 + 4);
        e[0] = a0.x; e[1] = a0.y; e[2] = a0.z; e[3] = a0.w;
        e[4] = a1.x; e[5] = a1.y; e[6] = a1.z; e[7] = a1.w;
        float m = -1e30f;
        #pragma unroll
        for (int p = 0; p < NPP; p++) m = fmaxf(m, e[p]);
        float s = 0.f;
        #pragma unroll
        for (int p = 0; p < NPP; p++) { e[p] = expf(e[p] - m); s += e[p]; }
        const float inv = 1.f / s;

        float L[16];
        #pragma unroll
        for (int q = 0; q < 4; q++)
            *(float4*)(L + q * 4) = *(const float4*)(g_loc + (size_t)(g0 + t) * 128 + h * 16 + q * 4);

        #pragma unroll
        for (int p = 0; p < NPP; p++) {
            const float aw = e[p] * inv;
            const float x = L[2 * p] * (float)WW - 0.5f;
            const float y = L[2 * p + 1] * (float)HH - 0.5f;
            const float xf = floorf(x), yf = floorf(y);
            const float wx = x - xf, wy = y - yf;
            const int x0 = (int)xf, y0 = (int)yf;
            const int x1 = x0 + 1,  y1 = y0 + 1;
            const int x0c = min(max(x0, 0), WW - 1), x1c = min(max(x1, 0), WW - 1);
            const int y0c = min(max(y0, 0), HH - 1), y1c = min(max(y1, 0), HH - 1);
            const bool vx0 = (x0 >= 0) & (x0 < WW);
            const bool vx1 = (x1 >= 0) & (x1 < WW);
            const bool vy0 = (y0 >= 0) & (y0 < HH);
            const bool vy1 = (y1 >= 0) & (y1 < HH);
            float wa = aw * (1.f - wx) * (1.f - wy);
            float wb = aw * wx * (1.f - wy);
            float wc = aw * (1.f - wx) * wy;
            float wd = aw * wx * wy;
            wa = (vx0 && vy0) ? wa : 0.f;
            wb = (vx1 && vy0) ? wb : 0.f;
            wc = (vx0 && vy1) ? wc : 0.f;
            wd = (vx1 && vy1) ? wd : 0.f;
            swgt4[p * 256 + tid] = make_float4(wa, wb, wc, wd);
            spak[p * 256 + tid] = (uint32_t)x0c | ((uint32_t)x1c << 8) |
                                  ((uint32_t)y0c << 16) | ((uint32_t)y1c << 24);
        }
    }
    __syncthreads();

    // ---- Phase 2: gather. warp = 4 pairs x 8 channel-lanes ----
    const int sub = lane >> 3;
    const int d4  = (lane & 7) * 4;

    for (int i = 0; i < 8; i++) {
        const int pid = w * 32 + i * 4 + sub;
        const int tt  = pid >> 3;
        const int h   = pid & 7;
        const float* vpb = g_vp + (size_t)((b * NHD + h) * HWSZ) * HDC + d4;
        float4 acc = make_float4(0.f, 0.f, 0.f, 0.f);
        #pragma unroll
        for (int p = 0; p < NPP; p++) {
            const float4 wv = swgt4[p * 256 + pid];
            const uint32_t pk = spak[p * 256 + pid];
            const int x0c = pk & 255, x1c = (pk >> 8) & 255;
            const int y0r = ((pk >> 16) & 255) << 6;
            const int y1r = (pk >> 24) << 6;
            const float4 v00 = *(const float4*)(vpb + ((y0r + x0c) << 5));
            const float4 v01 = *(const float4*)(vpb + ((y0r + x1c) << 5));
            const float4 v10 = *(const float4*)(vpb + ((y1r + x0c) << 5));
            const float4 v11 = *(const float4*)(vpb + ((y1r + x1c) << 5));
            acc.x += wv.x * v00.x + wv.y * v01.x + wv.z * v10.x + wv.w * v11.x;
            acc.y += wv.x * v00.y + wv.y * v01.y + wv.z * v10.y + wv.w * v11.y;
            acc.z += wv.x * v00.z + wv.y * v01.z + wv.z * v10.z + wv.w * v11.z;
            acc.w += wv.x * v00.w + wv.y * v01.w + wv.z * v10.w + wv.w * v11.w;
        }
        *(float4*)(smout + tt * 256 + h * 32 + d4) = acc;
    }
    __syncthreads();

    // convert + coalesced token-major write of bf16 hi/lo planes
    for (int idx = tid; idx < 32 * 32; idx += 256) {
        const int t = idx >> 5, k8 = (idx & 31) * 8;
        const float4 v0 = *(const float4*)(smout + t * 256 + k8);
        const float4 v1 = *(const float4*)(smout + t * 256 + k8 + 4);
        uint2 h0, l0, h1, l1;
        pack_hilo4(v0, h0, l0); pack_hilo4(v1, h1, l1);
        *(uint4*)(g_mh + (size_t)(g0 + t) * DIMC + k8) = make_uint4(h0.x, h0.y, h1.x, h1.y);
        *(uint4*)(g_ml + (size_t)(g0 + t) * DIMC + k8) = make_uint4(l0.x, l0.y, l1.x, l1.y);
    }
}

// ---------------------------------------------------------------------------
extern "C" void kernel_launch(void* const* d_in, const int* in_sizes, int n_in,
                              void* d_out, int out_size) {
    const float* query = (const float*)d_in[0];
    const float* value = (const float*)d_in[1];
    const float* Wloc  = (const float*)d_in[2];
    const float* bloc  = (const float*)d_in[3];
    const float* Watt  = (const float*)d_in[4];
    const float* batt  = (const float*)d_in[5];
    const float* Wval  = (const float*)d_in[6];
    const float* bval  = (const float*)d_in[7];
    const float* Wout  = (const float*)d_in[8];
    const float* bout  = (const float*)d_in[9];
    float* out = (float*)d_out;

    // smem per CTA: max(buffer 64K, stage 128*132*4 = 67.6K) + align pad
    const int smG = 128 * 132 * 4 + 1024;                            // 68608
    const int smsamp = (4 * 8 * 256 + 32 * 256) * 4 + 8 * 256 * 4;   // 73728
    cudaFuncSetAttribute(tc_gemm<1>, cudaFuncAttributeMaxDynamicSharedMemorySize, smG);
    cudaFuncSetAttribute(tc_gemm<3>, cudaFuncAttributeMaxDynamicSharedMemorySize, smG);
    cudaFuncSetAttribute(tc_gemm<0>, cudaFuncAttributeMaxDynamicSharedMemorySize, smG);
    cudaFuncSetAttribute(sampling_kernel, cudaFuncAttributeMaxDynamicSharedMemorySize, smsamp);

    const int MBLK = NG / 128;   // 128 tile-rows

    convert_act<<<1024, 256>>>(query, value);
    convert_w<<<96, 256>>>(Wloc, Watt, Wval, Wout);
    tc_gemm<1><<<dim3(MBLK, 2), 256, smG>>>(bloc, batt, nullptr);
    tc_gemm<3><<<dim3(MBLK, 2), 256, smG>>>(bval, nullptr, nullptr);
    sampling_kernel<<<NG / 32, 256, smsamp>>>();
    tc_gemm<0><<<dim3(MBLK, 2), 256, smG>>>(bout, nullptr, out);
}

// round 16
// speedup vs baseline: 1.1314x; 1.1314x over previous
#include <cuda_runtime.h>
#include <cuda_bf16.h>
#include <math.h>
#include <cstdint>

// Problem constants
#define BB   4
#define DIMC 256
#define HH   64
#define WW   64
#define HWSZ 4096
#define NHD  8
#define HDC  32
#define NPP  8
#define NG   (BB * HWSZ)      // 16384 tokens

// ---------------------------------------------------------------------------
// Scratch (device globals: no allocation allowed)
// ---------------------------------------------------------------------------
__device__ __align__(16) unsigned short g_qh[NG * DIMC];   // query bf16 hi, token-major
__device__ __align__(16) unsigned short g_ql[NG * DIMC];   // query bf16 lo
__device__ __align__(16) unsigned short g_vh[NG * DIMC];   // value bf16 hi
__device__ __align__(16) unsigned short g_vl[NG * DIMC];   // value bf16 lo
__device__ __align__(16) unsigned short g_mh[NG * DIMC];   // msda bf16 hi
__device__ __align__(16) unsigned short g_ml[NG * DIMC];   // msda bf16 lo
__device__ __align__(16) unsigned short g_w1h[192 * DIMC]; // [Wloc;Watt] hi
__device__ __align__(16) unsigned short g_w1l[192 * DIMC];
__device__ __align__(16) unsigned short g_w3h[256 * DIMC]; // Wval hi
__device__ __align__(16) unsigned short g_w3l[256 * DIMC];
__device__ __align__(16) unsigned short g_w0h[256 * DIMC]; // Wout hi
__device__ __align__(16) unsigned short g_w0l[256 * DIMC];

__device__ float g_vp [BB * NHD * HWSZ * HDC];   // v_proj, [b][h][yx][d]

// ---------------------------------------------------------------------------
// helpers (plain sm_103-compatible: ldmatrix + mma.sync + cp.async)
// ---------------------------------------------------------------------------
__device__ __forceinline__ uint32_t smem_u32(const void* p) {
    uint32_t a;
    asm("{ .reg .u64 t; cvta.to.shared.u64 t, %1; cvt.u32.u64 %0, t; }" : "=r"(a) : "l"(p));
    return a;
}
__device__ __forceinline__ void ldsm_x4(uint32_t (&r)[4], uint32_t addr) {
    asm volatile("ldmatrix.sync.aligned.m8n8.x4.shared.b16 {%0,%1,%2,%3}, [%4];"
        : "=r"(r[0]), "=r"(r[1]), "=r"(r[2]), "=r"(r[3]) : "r"(addr));
}
__device__ __forceinline__ void mma16816(float (&c)[4], const uint32_t (&a)[4],
                                         uint32_t b0, uint32_t b1) {
    asm volatile("mma.sync.aligned.m16n8k16.row.col.f32.bf16.bf16.f32 "
        "{%0,%1,%2,%3}, {%4,%5,%6,%7}, {%8,%9}, {%0,%1,%2,%3};"
        : "+f"(c[0]), "+f"(c[1]), "+f"(c[2]), "+f"(c[3])
        : "r"(a[0]), "r"(a[1]), "r"(a[2]), "r"(a[3]), "r"(b0), "r"(b1));
}
#define CP16(dst_u32, src_ptr) \
    asm volatile("cp.async.cg.shared.global [%0], [%1], 16;" :: "r"(dst_u32), "l"(src_ptr))
#define CP_COMMIT() asm volatile("cp.async.commit_group;" ::: "memory")
#define CP_WAIT0()  asm volatile("cp.async.wait_group 0;" ::: "memory")

__device__ __forceinline__ void pack_hilo4(float4 v, uint2& hi, uint2& lo) {
    __nv_bfloat16 h0 = __float2bfloat16(v.x), h1 = __float2bfloat16(v.y);
    __nv_bfloat16 h2 = __float2bfloat16(v.z), h3 = __float2bfloat16(v.w);
    __nv_bfloat16 l0 = __float2bfloat16(v.x - __bfloat162float(h0));
    __nv_bfloat16 l1 = __float2bfloat16(v.y - __bfloat162float(h1));
    __nv_bfloat16 l2 = __float2bfloat16(v.z - __bfloat162float(h2));
    __nv_bfloat16 l3 = __float2bfloat16(v.w - __bfloat162float(h3));
    hi.x = ((uint32_t)__bfloat16_as_ushort(h1) << 16) | __bfloat16_as_ushort(h0);
    hi.y = ((uint32_t)__bfloat16_as_ushort(h3) << 16) | __bfloat16_as_ushort(h2);
    lo.x = ((uint32_t)__bfloat16_as_ushort(l1) << 16) | __bfloat16_as_ushort(l0);
    lo.y = ((uint32_t)__bfloat16_as_ushort(l3) << 16) | __bfloat16_as_ushort(l2);
}

// ---------------------------------------------------------------------------
// convert_act: transpose query/value [b][k][4096] fp32 -> token-major bf16 hi/lo
// ---------------------------------------------------------------------------
__global__ __launch_bounds__(256)
void convert_act(const float* __restrict__ q, const float* __restrict__ v)
{
    __shared__ float sm[256 * 33];
    const int bi = blockIdx.x;
    const int tensor = bi >> 9;
    const int rem = bi & 511;
    const int b = rem >> 7, tile = rem & 127;
    const float* src = (tensor ? v : q) + (size_t)b * DIMC * HWSZ + tile * 32;

    for (int idx = threadIdx.x; idx < 2048; idx += 256) {
        const int k = idx >> 3, t4 = (idx & 7) * 4;
        const float4 val = *(const float4*)(src + (size_t)k * HWSZ + t4);
        sm[k * 33 + t4 + 0] = val.x;
        sm[k * 33 + t4 + 1] = val.y;
        sm[k * 33 + t4 + 2] = val.z;
        sm[k * 33 + t4 + 3] = val.w;
    }
    __syncthreads();

    unsigned short* dh = tensor ? g_vh : g_qh;
    unsigned short* dl = tensor ? g_vl : g_ql;
    const size_t g0 = (size_t)b * HWSZ + tile * 32;

    for (int idx = threadIdx.x; idx < 1024; idx += 256) {
        const int t = idx >> 5, k8 = (idx & 31) * 8;
        float4 v0, v1;
        v0.x = sm[(k8 + 0) * 33 + t]; v0.y = sm[(k8 + 1) * 33 + t];
        v0.z = sm[(k8 + 2) * 33 + t]; v0.w = sm[(k8 + 3) * 33 + t];
        v1.x = sm[(k8 + 4) * 33 + t]; v1.y = sm[(k8 + 5) * 33 + t];
        v1.z = sm[(k8 + 6) * 33 + t]; v1.w = sm[(k8 + 7) * 33 + t];
        uint2 h0, l0, h1, l1;
        pack_hilo4(v0, h0, l0); pack_hilo4(v1, h1, l1);
        *(uint4*)(dh + (g0 + t) * DIMC + k8) = make_uint4(h0.x, h0.y, h1.x, h1.y);
        *(uint4*)(dl + (g0 + t) * DIMC + k8) = make_uint4(l0.x, l0.y, l1.x, l1.y);
    }
}

// ---------------------------------------------------------------------------
// convert_w: weights fp32 -> bf16 hi/lo planes
// 704 rows: [0,192) = Wloc|Watt -> g_w1, [192,448) = Wval, [448,704) = Wout
// ---------------------------------------------------------------------------
__global__ __launch_bounds__(256)
void convert_w(const float* __restrict__ Wloc, const float* __restrict__ Watt,
               const float* __restrict__ Wval, const float* __restrict__ Wout)
{
    const int idx = blockIdx.x * 256 + threadIdx.x;
    if (idx >= 704 * 32) return;
    const int r = idx >> 5, k8 = (idx & 31) * 8;
    const float* src;
    unsigned short *dh, *dl;
    if (r < 192) {
        src = (r < 128) ? (Wloc + (size_t)r * DIMC) : (Watt + (size_t)(r - 128) * DIMC);
        dh = g_w1h + (size_t)r * DIMC; dl = g_w1l + (size_t)r * DIMC;
    } else if (r < 448) {
        const int rr = r - 192;
        src = Wval + (size_t)rr * DIMC;
        dh = g_w3h + (size_t)rr * DIMC; dl = g_w3l + (size_t)rr * DIMC;
    } else {
        const int rr = r - 448;
        src = Wout + (size_t)rr * DIMC;
        dh = g_w0h + (size_t)rr * DIMC; dl = g_w0l + (size_t)rr * DIMC;
    }
    const float4 v0 = *(const float4*)(src + k8);
    const float4 v1 = *(const float4*)(src + k8 + 4);
    uint2 h0, l0, h1, l1;
    pack_hilo4(v0, h0, l0); pack_hilo4(v1, h1, l1);
    *(uint4*)(dh + k8) = make_uint4(h0.x, h0.y, h1.x, h1.y);
    *(uint4*)(dl + k8) = make_uint4(l0.x, l0.y, l1.x, l1.y);
}

// ---------------------------------------------------------------------------
// bf16-split tensor-core GEMM (R13 structure): NT=256, 512 thr, K64 cp.async
// DST: 3 = vproj -> g_vp; 0 = out -> Cout
// ---------------------------------------------------------------------------
template<int DST>
__global__ __launch_bounds__(512, 1)
void tc_gemm(const float* __restrict__ bias, float* __restrict__ Cout)
{
    constexpr int NT = 256, NTH = 512;
    constexpr int BUFB = 32768 + 2 * NT * 128;

    extern __shared__ char smraw[];
    const uint32_t sb    = smem_u32(smraw);
    const uint32_t sbase = (sb + 1023) & ~1023u;
    char* smc = smraw + (sbase - sb);

    const int tid  = threadIdx.x;
    const int lane = tid & 31;
    const int wid  = tid >> 5;
    const int wm   = wid & 1;
    const int wn   = wid >> 1;

    const int m0  = blockIdx.x * 128;
    const int b   = m0 >> 12;
    const int yx0 = m0 & (HWSZ - 1);

    const char* Ah = (const char*)((DST == 3) ? g_vh : g_mh);
    const char* Al = (const char*)((DST == 3) ? g_vl : g_ml);
    const char* Wh = (const char*)((DST == 3) ? g_w3h : g_w0h);
    const char* Wl = (const char*)((DST == 3) ? g_w3l : g_w0l);

    auto load_chunk_async = [&](int c) {
        const uint32_t bufb = sbase + (c & 1) * BUFB;
        const int kB = c * 128;
        for (int idx = tid; idx < 1024; idx += NTH) {
            const int t = idx >> 3, ko = idx & 7;
            const size_t go = (size_t)(m0 + t) * 512 + kB + ko * 16;
            const uint32_t off = t * 128 + ((ko * 16) ^ ((t & 7) << 4));
            CP16(bufb + off, Ah + go);
            CP16(bufb + 16384 + off, Al + go);
        }
        for (int idx = tid; idx < NT * 8; idx += NTH) {
            const int n = idx >> 3, ko = idx & 7;
            const size_t go = (size_t)n * 512 + kB + ko * 16;
            const uint32_t off = n * 128 + ((ko * 16) ^ ((n & 7) << 4));
            CP16(bufb + 32768 + off, Wh + go);
            CP16(bufb + 32768 + NT * 128 + off, Wl + go);
        }
        CP_COMMIT();
    };

    load_chunk_async(0);
    CP_WAIT0();
    __syncthreads();

    float acc[4][4][4];
    #pragma unroll
    for (int i = 0; i < 4; i++)
        #pragma unroll
        for (int j = 0; j < 4; j++)
            #pragma unroll
            for (int q = 0; q < 4; q++) acc[i][j][q] = 0.f;

    const uint32_t khb = (lane >> 4) * 16;

    for (int c = 0; c < 4; c++) {
        if (c < 3) load_chunk_async(c + 1);
        const uint32_t bufb = sbase + (c & 1) * BUFB;
        #pragma unroll
        for (int ks = 0; ks < 4; ks++) {
            const uint32_t kb = ks * 32 + khb;
            uint32_t bh[2][4], bl[2][4];
            #pragma unroll
            for (int np = 0; np < 2; np++) {
                const int nr = wn * 32 + np * 16 + (lane & 15);
                const uint32_t off = nr * 128 + (kb ^ ((nr & 7) << 4));
                ldsm_x4(bh[np], bufb + 32768 + off);
                ldsm_x4(bl[np], bufb + 32768 + NT * 128 + off);
            }
            #pragma unroll
            for (int mt = 0; mt < 4; mt++) {
                const int mr = wm * 64 + mt * 16 + (lane & 15);
                const uint32_t off = mr * 128 + (kb ^ ((mr & 7) << 4));
                uint32_t ahf[4], alf[4];
                ldsm_x4(ahf, bufb + off);
                ldsm_x4(alf, bufb + 16384 + off);
                #pragma unroll
                for (int nt = 0; nt < 4; nt++) {
                    const int np = nt >> 1, hf = nt & 1;
                    mma16816(acc[mt][nt], ahf, bh[np][hf], bh[np][2 + hf]);
                    mma16816(acc[mt][nt], alf, bh[np][hf], bh[np][2 + hf]);
                    mma16816(acc[mt][nt], ahf, bl[np][hf], bl[np][2 + hf]);
                }
            }
        }
        if (c < 3) {
            CP_WAIT0();
            __syncthreads();
        }
    }
    __syncthreads();

    constexpr int NTP = 260;
    float* stage = (float*)smc;
    #pragma unroll
    for (int mt = 0; mt < 4; mt++) {
        const int r = wm * 64 + mt * 16 + (lane >> 2);
        #pragma unroll
        for (int nt = 0; nt < 4; nt++) {
            const int cl = wn * 32 + nt * 8 + (lane & 3) * 2;
            stage[r * NTP + cl]           = acc[mt][nt][0];
            stage[r * NTP + cl + 1]       = acc[mt][nt][1];
            stage[(r + 8) * NTP + cl]     = acc[mt][nt][2];
            stage[(r + 8) * NTP + cl + 1] = acc[mt][nt][3];
        }
    }
    __syncthreads();

    for (int idx = tid; idx < 128 * 64; idx += NTH) {
        const int t = idx >> 6;
        const int n = (idx & 63) * 4;
        float4 v = *(const float4*)(stage + t * NTP + n);
        const float4 bb4 = *(const float4*)(bias + n);
        v.x += bb4.x; v.y += bb4.y; v.z += bb4.z; v.w += bb4.w;
        if (DST == 3) {
            const int h = n >> 5, d = n & 31;
            *(float4*)(g_vp + ((size_t)((b * NHD + h) * HWSZ) + yx0 + t) * HDC + d) = v;
        } else {
            *(float4*)(Cout + (size_t)(m0 + t) * 256 + n) = v;
        }
    }
}

// ---------------------------------------------------------------------------
// gemm1_sampling: loc/att GEMM (MT=128, NT=192, 384 thr) with fused
// softmax + bilinear sampling epilogue. Needs g_vp ready. Writes g_mh/g_ml.
// smem: stage[128][196] (100352 B) | swgt4 (32768) | spak (8192) | smout (32768)
// ---------------------------------------------------------------------------
__global__ __launch_bounds__(384, 1)
void gemm1_sampling(const float* __restrict__ bloc, const float* __restrict__ batt)
{
    constexpr int NT = 192, NTH = 384;
    constexpr int BUFB = 32768 + 2 * NT * 128;   // 81920

    extern __shared__ char smraw[];
    const uint32_t sb    = smem_u32(smraw);
    const uint32_t sbase = (sb + 1023) & ~1023u;
    char* smc = smraw + (sbase - sb);

    const int tid  = threadIdx.x;
    const int lane = tid & 31;
    const int wid  = tid >> 5;
    const int wm   = wid & 1;        // 2 warp-rows
    const int wn   = wid >> 1;       // 6 warp-cols

    const int m0  = blockIdx.x * 128;
    const int b   = m0 >> 12;
    const int yx0 = m0 & (HWSZ - 1);

    const char* Ah = (const char*)g_qh;
    const char* Al = (const char*)g_ql;
    const char* Wh = (const char*)g_w1h;
    const char* Wl = (const char*)g_w1l;

    auto load_chunk_async = [&](int c) {
        const uint32_t bufb = sbase + (c & 1) * BUFB;
        const int kB = c * 128;
        for (int idx = tid; idx < 1024; idx += NTH) {
            const int t = idx >> 3, ko = idx & 7;
            const size_t go = (size_t)(m0 + t) * 512 + kB + ko * 16;
            const uint32_t off = t * 128 + ((ko * 16) ^ ((t & 7) << 4));
            CP16(bufb + off, Ah + go);
            CP16(bufb + 16384 + off, Al + go);
        }
        for (int idx = tid; idx < NT * 8; idx += NTH) {
            const int n = idx >> 3, ko = idx & 7;
            const size_t go = (size_t)n * 512 + kB + ko * 16;
            const uint32_t off = n * 128 + ((ko * 16) ^ ((n & 7) << 4));
            CP16(bufb + 32768 + off, Wh + go);
            CP16(bufb + 32768 + NT * 128 + off, Wl + go);
        }
        CP_COMMIT();
    };

    load_chunk_async(0);
    CP_WAIT0();
    __syncthreads();

    float acc[4][4][4];
    #pragma unroll
    for (int i = 0; i < 4; i++)
        #pragma unroll
        for (int j = 0; j < 4; j++)
            #pragma unroll
            for (int q = 0; q < 4; q++) acc[i][j][q] = 0.f;

    const uint32_t khb = (lane >> 4) * 16;

    for (int c = 0; c < 4; c++) {
        if (c < 3) load_chunk_async(c + 1);
        const uint32_t bufb = sbase + (c & 1) * BUFB;
        #pragma unroll
        for (int ks = 0; ks < 4; ks++) {
            const uint32_t kb = ks * 32 + khb;
            uint32_t bh[2][4], bl[2][4];
            #pragma unroll
            for (int np = 0; np < 2; np++) {
                const int nr = wn * 32 + np * 16 + (lane & 15);
                const uint32_t off = nr * 128 + (kb ^ ((nr & 7) << 4));
                ldsm_x4(bh[np], bufb + 32768 + off);
                ldsm_x4(bl[np], bufb + 32768 + NT * 128 + off);
            }
            #pragma unroll
            for (int mt = 0; mt < 4; mt++) {
                const int mr = wm * 64 + mt * 16 + (lane & 15);
                const uint32_t off = mr * 128 + (kb ^ ((mr & 7) << 4));
                uint32_t ahf[4], alf[4];
                ldsm_x4(ahf, bufb + off);
                ldsm_x4(alf, bufb + 16384 + off);
                #pragma unroll
                for (int nt = 0; nt < 4; nt++) {
                    const int np = nt >> 1, hf = nt & 1;
                    mma16816(acc[mt][nt], ahf, bh[np][hf], bh[np][2 + hf]);
                    mma16816(acc[mt][nt], alf, bh[np][hf], bh[np][2 + hf]);
                    mma16816(acc[mt][nt], ahf, bl[np][hf], bl[np][2 + hf]);
                }
            }
        }
        if (c < 3) {
            CP_WAIT0();
            __syncthreads();
        }
    }
    __syncthreads();

    // ---- frag -> stage (loc 0..127, att 128..191), bias added ----
    constexpr int NTP = 196;
    float* stage = (float*)smc;
    #pragma unroll
    for (int mt = 0; mt < 4; mt++) {
        const int r = wm * 64 + mt * 16 + (lane >> 2);
        #pragma unroll
        for (int nt = 0; nt < 4; nt++) {
            const int cl = wn * 32 + nt * 8 + (lane & 3) * 2;
            const float b0 = (cl < 128)     ? bloc[cl]       : batt[cl - 128];
            const float b1 = (cl + 1 < 128) ? bloc[cl + 1]   : batt[cl + 1 - 128];
            stage[r * NTP + cl]           = acc[mt][nt][0] + b0;
            stage[r * NTP + cl + 1]       = acc[mt][nt][1] + b1;
            stage[(r + 8) * NTP + cl]     = acc[mt][nt][2] + b0;
            stage[(r + 8) * NTP + cl + 1] = acc[mt][nt][3] + b1;
        }
    }
    __syncthreads();

    // ---- fused sampling over 4 subtiles of 32 tokens ----
    float4*   swgt4 = (float4*)(smc + 100352);
    uint32_t* spak  = (uint32_t*)(smc + 133120);
    float*    smout = (float*)(smc + 141312);

    for (int st = 0; st < 4; st++) {
        const int t0 = st * 32;

        // Phase 1: 256 pairs (t in subtile, h); threads 0..255
        if (tid < 256) {
            const int t = t0 + (tid >> 3), h = tid & 7;
            const float* srow = stage + t * NTP;
            float e[NPP];
            #pragma unroll
            for (int p = 0; p < NPP; p++) e[p] = srow[128 + h * 8 + p];
            float m = -1e30f;
            #pragma unroll
            for (int p = 0; p < NPP; p++) m = fmaxf(m, e[p]);
            float s = 0.f;
            #pragma unroll
            for (int p = 0; p < NPP; p++) { e[p] = expf(e[p] - m); s += e[p]; }
            const float inv = 1.f / s;

            #pragma unroll
            for (int p = 0; p < NPP; p++) {
                const float aw = e[p] * inv;
                const float x = srow[h * 16 + 2 * p]     * (float)WW - 0.5f;
                const float y = srow[h * 16 + 2 * p + 1] * (float)HH - 0.5f;
                const float xf = floorf(x), yf = floorf(y);
                const float wx = x - xf, wy = y - yf;
                const int x0 = (int)xf, y0 = (int)yf;
                const int x1 = x0 + 1,  y1 = y0 + 1;
                const int x0c = min(max(x0, 0), WW - 1), x1c = min(max(x1, 0), WW - 1);
                const int y0c = min(max(y0, 0), HH - 1), y1c = min(max(y1, 0), HH - 1);
                const bool vx0 = (x0 >= 0) & (x0 < WW);
                const bool vx1 = (x1 >= 0) & (x1 < WW);
                const bool vy0 = (y0 >= 0) & (y0 < HH);
                const bool vy1 = (y1 >= 0) & (y1 < HH);
                float wa = aw * (1.f - wx) * (1.f - wy);
                float wb = aw * wx * (1.f - wy);
                float wc = aw * (1.f - wx) * wy;
                float wd = aw * wx * wy;
                wa = (vx0 && vy0) ? wa : 0.f;
                wb = (vx1 && vy0) ? wb : 0.f;
                wc = (vx0 && vy1) ? wc : 0.f;
                wd = (vx1 && vy1) ? wd : 0.f;
                swgt4[p * 256 + tid] = make_float4(wa, wb, wc, wd);
                spak[p * 256 + tid] = (uint32_t)x0c | ((uint32_t)x1c << 8) |
                                      ((uint32_t)y0c << 16) | ((uint32_t)y1c << 24);
            }
        }
        __syncthreads();

        // Phase 2: gather. 12 warps, warp covers 4 pairs x 8 channel-lanes
        {
            const int sub = lane >> 3;
            const int d4  = (lane & 7) * 4;
            for (int i = 0; i < 6; i++) {
                const int pid = i * 48 + wid * 4 + sub;
                if (pid < 256) {
                    const int tt = pid >> 3;
                    const int h  = pid & 7;
                    const float* vpb = g_vp + (size_t)((b * NHD + h) * HWSZ) * HDC + d4;
                    float4 acc4 = make_float4(0.f, 0.f, 0.f, 0.f);
                    #pragma unroll
                    for (int p = 0; p < NPP; p++) {
                        const float4 wv = swgt4[p * 256 + pid];
                        const uint32_t pk = spak[p * 256 + pid];
                        const int x0c = pk & 255, x1c = (pk >> 8) & 255;
                        const int y0r = ((pk >> 16) & 255) << 6;
                        const int y1r = (pk >> 24) << 6;
                        const float4 v00 = *(const float4*)(vpb + ((y0r + x0c) << 5));
                        const float4 v01 = *(const float4*)(vpb + ((y0r + x1c) << 5));
                        const float4 v10 = *(const float4*)(vpb + ((y1r + x0c) << 5));
                        const float4 v11 = *(const float4*)(vpb + ((y1r + x1c) << 5));
                        acc4.x += wv.x * v00.x + wv.y * v01.x + wv.z * v10.x + wv.w * v11.x;
                        acc4.y += wv.x * v00.y + wv.y * v01.y + wv.z * v10.y + wv.w * v11.y;
                        acc4.z += wv.x * v00.z + wv.y * v01.z + wv.z * v10.z + wv.w * v11.z;
                        acc4.w += wv.x * v00.w + wv.y * v01.w + wv.z * v10.w + wv.w * v11.w;
                    }
                    *(float4*)(smout + tt * 256 + h * 32 + d4) = acc4;
                }
            }
        }
        __syncthreads();

        // Phase 3: convert + coalesced write of bf16 hi/lo planes
        for (int idx = tid; idx < 1024; idx += NTH) {
            const int t = idx >> 5, k8 = (idx & 31) * 8;
            const float4 v0 = *(const float4*)(smout + t * 256 + k8);
            const float4 v1 = *(const float4*)(smout + t * 256 + k8 + 4);
            uint2 h0, l0, h1, l1;
            pack_hilo4(v0, h0, l0); pack_hilo4(v1, h1, l1);
            const size_t g = (size_t)(m0 + t0 + t);
            *(uint4*)(g_mh + g * DIMC + k8) = make_uint4(h0.x, h0.y, h1.x, h1.y);
            *(uint4*)(g_ml + g * DIMC + k8) = make_uint4(l0.x, l0.y, l1.x, l1.y);
        }
        __syncthreads();   // before next subtile overwrites swgt/spak/smout
    }
}

// ---------------------------------------------------------------------------
extern "C" void kernel_launch(void* const* d_in, const int* in_sizes, int n_in,
                              void* d_out, int out_size) {
    const float* query = (const float*)d_in[0];
    const float* value = (const float*)d_in[1];
    const float* Wloc  = (const float*)d_in[2];
    const float* bloc  = (const float*)d_in[3];
    const float* Watt  = (const float*)d_in[4];
    const float* batt  = (const float*)d_in[5];
    const float* Wval  = (const float*)d_in[6];
    const float* bval  = (const float*)d_in[7];
    const float* Wout  = (const float*)d_in[8];
    const float* bout  = (const float*)d_in[9];
    float* out = (float*)d_out;

    const int sm256 = 2 * (32768 + 2 * 256 * 128) + 1024;   // 197632
    const int smF   = 174080 + 1024;                        // 175104
    cudaFuncSetAttribute(tc_gemm<3>, cudaFuncAttributeMaxDynamicSharedMemorySize, sm256);
    cudaFuncSetAttribute(tc_gemm<0>, cudaFuncAttributeMaxDynamicSharedMemorySize, sm256);
    cudaFuncSetAttribute(gemm1_sampling, cudaFuncAttributeMaxDynamicSharedMemorySize, smF);

    const int MBLK = NG / 128;   // 128 CTAs

    convert_act<<<1024, 256>>>(query, value);
    convert_w<<<88, 256>>>(Wloc, Watt, Wval, Wout);
    tc_gemm<3><<<MBLK, 512, sm256>>>(bval, nullptr);
    gemm1_sampling<<<MBLK, 384, smF>>>(bloc, batt);
    tc_gemm<0><<<MBLK, 512, sm256>>>(bout, out);
}

// round 17
// speedup vs baseline: 1.1345x; 1.0028x over previous
#include <cuda_runtime.h>
#include <cuda_bf16.h>
#include <math.h>
#include <cstdint>

// Problem constants
#define BB   4
#define DIMC 256
#define HH   64
#define WW   64
#define HWSZ 4096
#define NHD  8
#define HDC  32
#define NPP  8
#define NG   (BB * HWSZ)      // 16384 tokens

// ---------------------------------------------------------------------------
// Scratch (device globals: no allocation allowed)
// ---------------------------------------------------------------------------
__device__ __align__(16) unsigned short g_qh[NG * DIMC];   // query bf16 hi, token-major
__device__ __align__(16) unsigned short g_ql[NG * DIMC];   // query bf16 lo
__device__ __align__(16) unsigned short g_vh[NG * DIMC];   // value bf16 hi
__device__ __align__(16) unsigned short g_vl[NG * DIMC];   // value bf16 lo
__device__ __align__(16) unsigned short g_mh[NG * DIMC];   // msda bf16 hi
__device__ __align__(16) unsigned short g_ml[NG * DIMC];   // msda bf16 lo
__device__ __align__(16) unsigned short g_w1h[192 * DIMC]; // [Wloc;Watt] hi
__device__ __align__(16) unsigned short g_w1l[192 * DIMC];
__device__ __align__(16) unsigned short g_w3h[256 * DIMC]; // Wval hi
__device__ __align__(16) unsigned short g_w3l[256 * DIMC];
__device__ __align__(16) unsigned short g_w0h[256 * DIMC]; // Wout hi
__device__ __align__(16) unsigned short g_w0l[256 * DIMC];

__device__ float g_vp [BB * NHD * HWSZ * HDC];   // v_proj, [b][h][yx][d]

// ---------------------------------------------------------------------------
// helpers (plain sm_103-compatible: ldmatrix + mma.sync + cp.async)
// ---------------------------------------------------------------------------
__device__ __forceinline__ uint32_t smem_u32(const void* p) {
    uint32_t a;
    asm("{ .reg .u64 t; cvta.to.shared.u64 t, %1; cvt.u32.u64 %0, t; }" : "=r"(a) : "l"(p));
    return a;
}
__device__ __forceinline__ void ldsm_x4(uint32_t (&r)[4], uint32_t addr) {
    asm volatile("ldmatrix.sync.aligned.m8n8.x4.shared.b16 {%0,%1,%2,%3}, [%4];"
        : "=r"(r[0]), "=r"(r[1]), "=r"(r[2]), "=r"(r[3]) : "r"(addr));
}
__device__ __forceinline__ void mma16816(float (&c)[4], const uint32_t (&a)[4],
                                         uint32_t b0, uint32_t b1) {
    asm volatile("mma.sync.aligned.m16n8k16.row.col.f32.bf16.bf16.f32 "
        "{%0,%1,%2,%3}, {%4,%5,%6,%7}, {%8,%9}, {%0,%1,%2,%3};"
        : "+f"(c[0]), "+f"(c[1]), "+f"(c[2]), "+f"(c[3])
        : "r"(a[0]), "r"(a[1]), "r"(a[2]), "r"(a[3]), "r"(b0), "r"(b1));
}
#define CP16(dst_u32, src_ptr) \
    asm volatile("cp.async.cg.shared.global [%0], [%1], 16;" :: "r"(dst_u32), "l"(src_ptr))
#define CP_COMMIT() asm volatile("cp.async.commit_group;" ::: "memory")
#define CP_WAIT0()  asm volatile("cp.async.wait_group 0;" ::: "memory")

__device__ __forceinline__ void pack_hilo4(float4 v, uint2& hi, uint2& lo) {
    __nv_bfloat16 h0 = __float2bfloat16(v.x), h1 = __float2bfloat16(v.y);
    __nv_bfloat16 h2 = __float2bfloat16(v.z), h3 = __float2bfloat16(v.w);
    __nv_bfloat16 l0 = __float2bfloat16(v.x - __bfloat162float(h0));
    __nv_bfloat16 l1 = __float2bfloat16(v.y - __bfloat162float(h1));
    __nv_bfloat16 l2 = __float2bfloat16(v.z - __bfloat162float(h2));
    __nv_bfloat16 l3 = __float2bfloat16(v.w - __bfloat162float(h3));
    hi.x = ((uint32_t)__bfloat16_as_ushort(h1) << 16) | __bfloat16_as_ushort(h0);
    hi.y = ((uint32_t)__bfloat16_as_ushort(h3) << 16) | __bfloat16_as_ushort(h2);
    lo.x = ((uint32_t)__bfloat16_as_ushort(l1) << 16) | __bfloat16_as_ushort(l0);
    lo.y = ((uint32_t)__bfloat16_as_ushort(l3) << 16) | __bfloat16_as_ushort(l2);
}

// ---------------------------------------------------------------------------
// convert_act: transpose query/value [b][k][4096] fp32 -> token-major bf16 hi/lo
// ---------------------------------------------------------------------------
__global__ __launch_bounds__(256)
void convert_act(const float* __restrict__ q, const float* __restrict__ v)
{
    __shared__ float sm[256 * 33];
    const int bi = blockIdx.x;
    const int tensor = bi >> 9;
    const int rem = bi & 511;
    const int b = rem >> 7, tile = rem & 127;
    const float* src = (tensor ? v : q) + (size_t)b * DIMC * HWSZ + tile * 32;

    for (int idx = threadIdx.x; idx < 2048; idx += 256) {
        const int k = idx >> 3, t4 = (idx & 7) * 4;
        const float4 val = *(const float4*)(src + (size_t)k * HWSZ + t4);
        sm[k * 33 + t4 + 0] = val.x;
        sm[k * 33 + t4 + 1] = val.y;
        sm[k * 33 + t4 + 2] = val.z;
        sm[k * 33 + t4 + 3] = val.w;
    }
    __syncthreads();

    unsigned short* dh = tensor ? g_vh : g_qh;
    unsigned short* dl = tensor ? g_vl : g_ql;
    const size_t g0 = (size_t)b * HWSZ + tile * 32;

    for (int idx = threadIdx.x; idx < 1024; idx += 256) {
        const int t = idx >> 5, k8 = (idx & 31) * 8;
        float4 v0, v1;
        v0.x = sm[(k8 + 0) * 33 + t]; v0.y = sm[(k8 + 1) * 33 + t];
        v0.z = sm[(k8 + 2) * 33 + t]; v0.w = sm[(k8 + 3) * 33 + t];
        v1.x = sm[(k8 + 4) * 33 + t]; v1.y = sm[(k8 + 5) * 33 + t];
        v1.z = sm[(k8 + 6) * 33 + t]; v1.w = sm[(k8 + 7) * 33 + t];
        uint2 h0, l0, h1, l1;
        pack_hilo4(v0, h0, l0); pack_hilo4(v1, h1, l1);
        *(uint4*)(dh + (g0 + t) * DIMC + k8) = make_uint4(h0.x, h0.y, h1.x, h1.y);
        *(uint4*)(dl + (g0 + t) * DIMC + k8) = make_uint4(l0.x, l0.y, l1.x, l1.y);
    }
}

// ---------------------------------------------------------------------------
// convert_w: weights fp32 -> bf16 hi/lo planes
// 704 rows: [0,192) = Wloc|Watt -> g_w1, [192,448) = Wval, [448,704) = Wout
// ---------------------------------------------------------------------------
__global__ __launch_bounds__(256)
void convert_w(const float* __restrict__ Wloc, const float* __restrict__ Watt,
               const float* __restrict__ Wval, const float* __restrict__ Wout)
{
    const int idx = blockIdx.x * 256 + threadIdx.x;
    if (idx >= 704 * 32) return;
    const int r = idx >> 5, k8 = (idx & 31) * 8;
    const float* src;
    unsigned short *dh, *dl;
    if (r < 192) {
        src = (r < 128) ? (Wloc + (size_t)r * DIMC) : (Watt + (size_t)(r - 128) * DIMC);
        dh = g_w1h + (size_t)r * DIMC; dl = g_w1l + (size_t)r * DIMC;
    } else if (r < 448) {
        const int rr = r - 192;
        src = Wval + (size_t)rr * DIMC;
        dh = g_w3h + (size_t)rr * DIMC; dl = g_w3l + (size_t)rr * DIMC;
    } else {
        const int rr = r - 448;
        src = Wout + (size_t)rr * DIMC;
        dh = g_w0h + (size_t)rr * DIMC; dl = g_w0l + (size_t)rr * DIMC;
    }
    const float4 v0 = *(const float4*)(src + k8);
    const float4 v1 = *(const float4*)(src + k8 + 4);
    uint2 h0, l0, h1, l1;
    pack_hilo4(v0, h0, l0); pack_hilo4(v1, h1, l1);
    *(uint4*)(dh + k8) = make_uint4(h0.x, h0.y, h1.x, h1.y);
    *(uint4*)(dl + k8) = make_uint4(l0.x, l0.y, l1.x, l1.y);
}

// ---------------------------------------------------------------------------
// bf16-split tensor-core GEMM (R13 structure): NT=256, 512 thr, K64 cp.async
// DST: 3 = vproj -> g_vp; 0 = out -> Cout
// ---------------------------------------------------------------------------
template<int DST>
__global__ __launch_bounds__(512, 1)
void tc_gemm(const float* __restrict__ bias, float* __restrict__ Cout)
{
    constexpr int NT = 256, NTH = 512;
    constexpr int BUFB = 32768 + 2 * NT * 128;

    extern __shared__ char smraw[];
    const uint32_t sb    = smem_u32(smraw);
    const uint32_t sbase = (sb + 1023) & ~1023u;
    char* smc = smraw + (sbase - sb);

    const int tid  = threadIdx.x;
    const int lane = tid & 31;
    const int wid  = tid >> 5;
    const int wm   = wid & 1;
    const int wn   = wid >> 1;

    const int m0  = blockIdx.x * 128;
    const int b   = m0 >> 12;
    const int yx0 = m0 & (HWSZ - 1);

    const char* Ah = (const char*)((DST == 3) ? g_vh : g_mh);
    const char* Al = (const char*)((DST == 3) ? g_vl : g_ml);
    const char* Wh = (const char*)((DST == 3) ? g_w3h : g_w0h);
    const char* Wl = (const char*)((DST == 3) ? g_w3l : g_w0l);

    auto load_chunk_async = [&](int c) {
        const uint32_t bufb = sbase + (c & 1) * BUFB;
        const int kB = c * 128;
        for (int idx = tid; idx < 1024; idx += NTH) {
            const int t = idx >> 3, ko = idx & 7;
            const size_t go = (size_t)(m0 + t) * 512 + kB + ko * 16;
            const uint32_t off = t * 128 + ((ko * 16) ^ ((t & 7) << 4));
            CP16(bufb + off, Ah + go);
            CP16(bufb + 16384 + off, Al + go);
        }
        for (int idx = tid; idx < NT * 8; idx += NTH) {
            const int n = idx >> 3, ko = idx & 7;
            const size_t go = (size_t)n * 512 + kB + ko * 16;
            const uint32_t off = n * 128 + ((ko * 16) ^ ((n & 7) << 4));
            CP16(bufb + 32768 + off, Wh + go);
            CP16(bufb + 32768 + NT * 128 + off, Wl + go);
        }
        CP_COMMIT();
    };

    load_chunk_async(0);
    CP_WAIT0();
    __syncthreads();

    float acc[4][4][4];
    #pragma unroll
    for (int i = 0; i < 4; i++)
        #pragma unroll
        for (int j = 0; j < 4; j++)
            #pragma unroll
            for (int q = 0; q < 4; q++) acc[i][j][q] = 0.f;

    const uint32_t khb = (lane >> 4) * 16;

    for (int c = 0; c < 4; c++) {
        if (c < 3) load_chunk_async(c + 1);
        const uint32_t bufb = sbase + (c & 1) * BUFB;
        #pragma unroll
        for (int ks = 0; ks < 4; ks++) {
            const uint32_t kb = ks * 32 + khb;
            uint32_t bh[2][4], bl[2][4];
            #pragma unroll
            for (int np = 0; np < 2; np++) {
                const int nr = wn * 32 + np * 16 + (lane & 15);
                const uint32_t off = nr * 128 + (kb ^ ((nr & 7) << 4));
                ldsm_x4(bh[np], bufb + 32768 + off);
                ldsm_x4(bl[np], bufb + 32768 + NT * 128 + off);
            }
            #pragma unroll
            for (int mt = 0; mt < 4; mt++) {
                const int mr = wm * 64 + mt * 16 + (lane & 15);
                const uint32_t off = mr * 128 + (kb ^ ((mr & 7) << 4));
                uint32_t ahf[4], alf[4];
                ldsm_x4(ahf, bufb + off);
                ldsm_x4(alf, bufb + 16384 + off);
                #pragma unroll
                for (int nt = 0; nt < 4; nt++) {
                    const int np = nt >> 1, hf = nt & 1;
                    mma16816(acc[mt][nt], ahf, bh[np][hf], bh[np][2 + hf]);
                    mma16816(acc[mt][nt], alf, bh[np][hf], bh[np][2 + hf]);
                    mma16816(acc[mt][nt], ahf, bl[np][hf], bl[np][2 + hf]);
                }
            }
        }
        if (c < 3) {
            CP_WAIT0();
            __syncthreads();
        }
    }
    __syncthreads();

    constexpr int NTP = 260;
    float* stage = (float*)smc;
    #pragma unroll
    for (int mt = 0; mt < 4; mt++) {
        const int r = wm * 64 + mt * 16 + (lane >> 2);
        #pragma unroll
        for (int nt = 0; nt < 4; nt++) {
            const int cl = wn * 32 + nt * 8 + (lane & 3) * 2;
            stage[r * NTP + cl]           = acc[mt][nt][0];
            stage[r * NTP + cl + 1]       = acc[mt][nt][1];
            stage[(r + 8) * NTP + cl]     = acc[mt][nt][2];
            stage[(r + 8) * NTP + cl + 1] = acc[mt][nt][3];
        }
    }
    __syncthreads();

    for (int idx = tid; idx < 128 * 64; idx += NTH) {
        const int t = idx >> 6;
        const int n = (idx & 63) * 4;
        float4 v = *(const float4*)(stage + t * NTP + n);
        const float4 bb4 = *(const float4*)(bias + n);
        v.x += bb4.x; v.y += bb4.y; v.z += bb4.z; v.w += bb4.w;
        if (DST == 3) {
            const int h = n >> 5, d = n & 31;
            *(float4*)(g_vp + ((size_t)((b * NHD + h) * HWSZ) + yx0 + t) * HDC + d) = v;
        } else {
            *(float4*)(Cout + (size_t)(m0 + t) * 256 + n) = v;
        }
    }
}

// ---------------------------------------------------------------------------
// gemm1_sampling: loc/att GEMM (MT=128, NT=192) + fused softmax/bilinear sampling.
// 512 threads, 16 warps: warp grid 4(M rows of 32) x 4(N cols of 48).
// Needs g_vp ready. Writes g_mh/g_ml.
// smem: stage[128][196] (100352 B) | swgt4 (32768) | spak (8192) | smout (32768)
// ---------------------------------------------------------------------------
__global__ __launch_bounds__(512, 1)
void gemm1_sampling(const float* __restrict__ bloc, const float* __restrict__ batt)
{
    constexpr int NT = 192, NTH = 512;
    constexpr int BUFB = 32768 + 2 * NT * 128;   // 81920

    extern __shared__ char smraw[];
    const uint32_t sb    = smem_u32(smraw);
    const uint32_t sbase = (sb + 1023) & ~1023u;
    char* smc = smraw + (sbase - sb);

    const int tid  = threadIdx.x;
    const int lane = tid & 31;
    const int wid  = tid >> 5;
    const int wm   = wid & 3;        // 4 warp-rows (32 tokens each)
    const int wn   = wid >> 2;       // 4 warp-cols (48 cols each)

    const int m0  = blockIdx.x * 128;
    const int b   = m0 >> 12;

    const char* Ah = (const char*)g_qh;
    const char* Al = (const char*)g_ql;
    const char* Wh = (const char*)g_w1h;
    const char* Wl = (const char*)g_w1l;

    auto load_chunk_async = [&](int c) {
        const uint32_t bufb = sbase + (c & 1) * BUFB;
        const int kB = c * 128;
        for (int idx = tid; idx < 1024; idx += NTH) {
            const int t = idx >> 3, ko = idx & 7;
            const size_t go = (size_t)(m0 + t) * 512 + kB + ko * 16;
            const uint32_t off = t * 128 + ((ko * 16) ^ ((t & 7) << 4));
            CP16(bufb + off, Ah + go);
            CP16(bufb + 16384 + off, Al + go);
        }
        for (int idx = tid; idx < NT * 8; idx += NTH) {
            const int n = idx >> 3, ko = idx & 7;
            const size_t go = (size_t)n * 512 + kB + ko * 16;
            const uint32_t off = n * 128 + ((ko * 16) ^ ((n & 7) << 4));
            CP16(bufb + 32768 + off, Wh + go);
            CP16(bufb + 32768 + NT * 128 + off, Wl + go);
        }
        CP_COMMIT();
    };

    load_chunk_async(0);
    CP_WAIT0();
    __syncthreads();

    float acc[2][6][4];
    #pragma unroll
    for (int i = 0; i < 2; i++)
        #pragma unroll
        for (int j = 0; j < 6; j++)
            #pragma unroll
            for (int q = 0; q < 4; q++) acc[i][j][q] = 0.f;

    const uint32_t khb = (lane >> 4) * 16;

    for (int c = 0; c < 4; c++) {
        if (c < 3) load_chunk_async(c + 1);
        const uint32_t bufb = sbase + (c & 1) * BUFB;
        #pragma unroll
        for (int ks = 0; ks < 4; ks++) {
            const uint32_t kb = ks * 32 + khb;
            uint32_t bh[3][4], bl[3][4];
            #pragma unroll
            for (int np = 0; np < 3; np++) {
                const int nr = wn * 48 + np * 16 + (lane & 15);
                const uint32_t off = nr * 128 + (kb ^ ((nr & 7) << 4));
                ldsm_x4(bh[np], bufb + 32768 + off);
                ldsm_x4(bl[np], bufb + 32768 + NT * 128 + off);
            }
            #pragma unroll
            for (int mt = 0; mt < 2; mt++) {
                const int mr = wm * 32 + mt * 16 + (lane & 15);
                const uint32_t off = mr * 128 + (kb ^ ((mr & 7) << 4));
                uint32_t ahf[4], alf[4];
                ldsm_x4(ahf, bufb + off);
                ldsm_x4(alf, bufb + 16384 + off);
                #pragma unroll
                for (int nt = 0; nt < 6; nt++) {
                    const int np = nt >> 1, hf = nt & 1;
                    mma16816(acc[mt][nt], ahf, bh[np][hf], bh[np][2 + hf]);
                    mma16816(acc[mt][nt], alf, bh[np][hf], bh[np][2 + hf]);
                    mma16816(acc[mt][nt], ahf, bl[np][hf], bl[np][2 + hf]);
                }
            }
        }
        if (c < 3) {
            CP_WAIT0();
            __syncthreads();
        }
    }
    __syncthreads();

    // ---- frag -> stage (loc 0..127, att 128..191), bias added ----
    constexpr int NTP = 196;
    float* stage = (float*)smc;
    #pragma unroll
    for (int mt = 0; mt < 2; mt++) {
        const int r = wm * 32 + mt * 16 + (lane >> 2);
        #pragma unroll
        for (int nt = 0; nt < 6; nt++) {
            const int cl = wn * 48 + nt * 8 + (lane & 3) * 2;
            const float b0 = (cl < 128)     ? bloc[cl]       : batt[cl - 128];
            const float b1 = (cl + 1 < 128) ? bloc[cl + 1]   : batt[cl + 1 - 128];
            stage[r * NTP + cl]           = acc[mt][nt][0] + b0;
            stage[r * NTP + cl + 1]       = acc[mt][nt][1] + b1;
            stage[(r + 8) * NTP + cl]     = acc[mt][nt][2] + b0;
            stage[(r + 8) * NTP + cl + 1] = acc[mt][nt][3] + b1;
        }
    }
    __syncthreads();

    // ---- fused sampling over 4 subtiles of 32 tokens ----
    float4*   swgt4 = (float4*)(smc + 100352);
    uint32_t* spak  = (uint32_t*)(smc + 133120);
    float*    smout = (float*)(smc + 141312);

    for (int st = 0; st < 4; st++) {
        const int t0 = st * 32;

        // Phase 1: 256 pairs (t in subtile, h); threads 0..255
        if (tid < 256) {
            const int t = t0 + (tid >> 3), h = tid & 7;
            const float* srow = stage + t * NTP;
            float e[NPP];
            #pragma unroll
            for (int p = 0; p < NPP; p++) e[p] = srow[128 + h * 8 + p];
            float m = -1e30f;
            #pragma unroll
            for (int p = 0; p < NPP; p++) m = fmaxf(m, e[p]);
            float s = 0.f;
            #pragma unroll
            for (int p = 0; p < NPP; p++) { e[p] = expf(e[p] - m); s += e[p]; }
            const float inv = 1.f / s;

            #pragma unroll
            for (int p = 0; p < NPP; p++) {
                const float aw = e[p] * inv;
                const float x = srow[h * 16 + 2 * p]     * (float)WW - 0.5f;
                const float y = srow[h * 16 + 2 * p + 1] * (float)HH - 0.5f;
                const float xf = floorf(x), yf = floorf(y);
                const float wx = x - xf, wy = y - yf;
                const int x0 = (int)xf, y0 = (int)yf;
                const int x1 = x0 + 1,  y1 = y0 + 1;
                const int x0c = min(max(x0, 0), WW - 1), x1c = min(max(x1, 0), WW - 1);
                const int y0c = min(max(y0, 0), HH - 1), y1c = min(max(y1, 0), HH - 1);
                const bool vx0 = (x0 >= 0) & (x0 < WW);
                const bool vx1 = (x1 >= 0) & (x1 < WW);
                const bool vy0 = (y0 >= 0) & (y0 < HH);
                const bool vy1 = (y1 >= 0) & (y1 < HH);
                float wa = aw * (1.f - wx) * (1.f - wy);
                float wb = aw * wx * (1.f - wy);
                float wc = aw * (1.f - wx) * wy;
                float wd = aw * wx * wy;
                wa = (vx0 && vy0) ? wa : 0.f;
                wb = (vx1 && vy0) ? wb : 0.f;
                wc = (vx0 && vy1) ? wc : 0.f;
                wd = (vx1 && vy1) ? wd : 0.f;
                swgt4[p * 256 + tid] = make_float4(wa, wb, wc, wd);
                spak[p * 256 + tid] = (uint32_t)x0c | ((uint32_t)x1c << 8) |
                                      ((uint32_t)y0c << 16) | ((uint32_t)y1c << 24);
            }
        }
        __syncthreads();

        // Phase 2: gather. 16 warps x 4 pairs x 8 channel-lanes
        {
            const int sub = lane >> 3;
            const int d4  = (lane & 7) * 4;
            #pragma unroll
            for (int i = 0; i < 4; i++) {
                const int pid = i * 64 + wid * 4 + sub;   // 0..255
                const int tt = pid >> 3;
                const int h  = pid & 7;
                const float* vpb = g_vp + (size_t)((b * NHD + h) * HWSZ) * HDC + d4;
                float4 acc4 = make_float4(0.f, 0.f, 0.f, 0.f);
                #pragma unroll
                for (int p = 0; p < NPP; p++) {
                    const float4 wv = swgt4[p * 256 + pid];
                    const uint32_t pk = spak[p * 256 + pid];
                    const int x0c = pk & 255, x1c = (pk >> 8) & 255;
                    const int y0r = ((pk >> 16) & 255) << 6;
                    const int y1r = (pk >> 24) << 6;
                    const float4 v00 = *(const float4*)(vpb + ((y0r + x0c) << 5));
                    const float4 v01 = *(const float4*)(vpb + ((y0r + x1c) << 5));
                    const float4 v10 = *(const float4*)(vpb + ((y1r + x0c) << 5));
                    const float4 v11 = *(const float4*)(vpb + ((y1r + x1c) << 5));
                    acc4.x += wv.x * v00.x + wv.y * v01.x + wv.z * v10.x + wv.w * v11.x;
                    acc4.y += wv.x * v00.y + wv.y * v01.y + wv.z * v10.y + wv.w * v11.y;
                    acc4.z += wv.x * v00.z + wv.y * v01.z + wv.z * v10.z + wv.w * v11.z;
                    acc4.w += wv.x * v00.w + wv.y * v01.w + wv.z * v10.w + wv.w * v11.w;
                }
                *(float4*)(smout + tt * 256 + h * 32 + d4) = acc4;
            }
        }
        __syncthreads();

        // Phase 3: convert + coalesced write of bf16 hi/lo planes
        for (int idx = tid; idx < 1024; idx += NTH) {
            const int t = idx >> 5, k8 = (idx & 31) * 8;
            const float4 v0 = *(const float4*)(smout + t * 256 + k8);
            const float4 v1 = *(const float4*)(smout + t * 256 + k8 + 4);
            uint2 h0, l0, h1, l1;
            pack_hilo4(v0, h0, l0); pack_hilo4(v1, h1, l1);
            const size_t g = (size_t)(m0 + t0 + t);
            *(uint4*)(g_mh + g * DIMC + k8) = make_uint4(h0.x, h0.y, h1.x, h1.y);
            *(uint4*)(g_ml + g * DIMC + k8) = make_uint4(l0.x, l0.y, l1.x, l1.y);
        }
        __syncthreads();   // before next subtile overwrites swgt/spak/smout
    }
}

// ---------------------------------------------------------------------------
extern "C" void kernel_launch(void* const* d_in, const int* in_sizes, int n_in,
                              void* d_out, int out_size) {
    const float* query = (const float*)d_in[0];
    const float* value = (const float*)d_in[1];
    const float* Wloc  = (const float*)d_in[2];
    const float* bloc  = (const float*)d_in[3];
    const float* Watt  = (const float*)d_in[4];
    const float* batt  = (const float*)d_in[5];
    const float* Wval  = (const float*)d_in[6];
    const float* bval  = (const float*)d_in[7];
    const float* Wout  = (const float*)d_in[8];
    const float* bout  = (const float*)d_in[9];
    float* out = (float*)d_out;

    const int sm256 = 2 * (32768 + 2 * 256 * 128) + 1024;   // 197632
    const int smF   = 174080 + 1024;                        // 175104
    cudaFuncSetAttribute(tc_gemm<3>, cudaFuncAttributeMaxDynamicSharedMemorySize, sm256);
    cudaFuncSetAttribute(tc_gemm<0>, cudaFuncAttributeMaxDynamicSharedMemorySize, sm256);
    cudaFuncSetAttribute(gemm1_sampling, cudaFuncAttributeMaxDynamicSharedMemorySize, smF);

    const int MBLK = NG / 128;   // 128 CTAs

    convert_act<<<1024, 256>>>(query, value);
    convert_w<<<88, 256>>>(Wloc, Watt, Wval, Wout);
    tc_gemm<3><<<MBLK, 512, sm256>>>(bval, nullptr);
    gemm1_sampling<<<MBLK, 512, smF>>>(bloc, batt);
    tc_gemm<0><<<MBLK, 512, sm256>>>(bout, out);
}